// round 14
// baseline (speedup 1.0000x reference)
#include <cuda_runtime.h>

#define ESP 1e-12f
#define C_DIM 8192
#define THREADS 512
#define GROUP   256          // threads per row (the proven R9 engine width)

__device__ double        g_accum;   // zero-init; reset by finalizer each run
__device__ unsigned int  g_ticket;  // zero-init; reset by finalizer each run

__device__ __forceinline__ float fsqrt_approx(float x) {
    float r;
    asm("sqrt.approx.f32 %0, %1;" : "=f"(r) : "f"(x));
    return r;
}

// 512-thread blocks, 2 rows per block, 256 threads per row: the exact R9
// per-row load engine (8 float4-pairs/thread) with halved CTA count.
// LB(512,4) pins regs<=32 -> 4 CTAs/SM = 2048 thr/SM, same occupancy as R9.
__global__ void __launch_bounds__(THREADS, 4) mfl_fused_kernel(
    const float* __restrict__ p,
    const float* __restrict__ g,
    float* __restrict__ out,
    int n_rows)
{
    const int tid  = threadIdx.x;
    const int half = tid >> 8;           // 0 or 1: which of the 2 rows
    const int gtid = tid & (GROUP - 1);  // lane within the 256-thread group
    const int row  = blockIdx.x * 2 + half;

    const float4* __restrict__ p4 =
        reinterpret_cast<const float4*>(p + (size_t)row * C_DIM);
    const float4* __restrict__ g4 =
        reinterpret_cast<const float4*>(g + (size_t)row * C_DIM);

    float sum = 0.0f;
    int   cnt = 0;

    // 2048 float4s per row / 256 threads -> 8 iterations (identical to R9).
    #pragma unroll
    for (int i = 0; i < 8; i++) {
        float4 pv = __ldcs(&p4[gtid + i * GROUP]);
        float4 gv = __ldcs(&g4[gtid + i * GROUP]);

        #pragma unroll
        for (int k = 0; k < 4; k++) {
            float pe = (&pv.x)[k];
            float ge = (&gv.x)[k];
            float a = fmaf(pe, ge, ESP);
            float b = fmaf(1.0f - pe, 1.0f - ge, ESP);
            float l = 1.0f - (fsqrt_approx(a) + fsqrt_approx(b));
            bool nz = (ge != 0.0f);
            sum += nz ? l : 0.0f;
            cnt += nz ? 1 : 0;
        }
    }

    // Warp reduction
    #pragma unroll
    for (int o = 16; o > 0; o >>= 1) {
        sum += __shfl_down_sync(0xffffffffu, sum, o);
        cnt += __shfl_down_sync(0xffffffffu, cnt, o);
    }

    // 16 warps: warps 0-7 = row half 0, warps 8-15 = row half 1.
    __shared__ float s_sum[THREADS / 32];
    __shared__ int   s_cnt[THREADS / 32];
    const int wid = tid >> 5;
    const int lid = tid & 31;
    if (lid == 0) {
        s_sum[wid] = sum;
        s_cnt[wid] = cnt;
    }
    __syncthreads();

    // One finalizer thread per row half.
    if (gtid == 0) {
        const int base = half * 8;
        float bsum = 0.0f;
        int   bcnt = 0;
        #pragma unroll
        for (int w = 0; w < 8; w++) {
            bsum += s_sum[base + w];
            bcnt += s_cnt[base + w];
        }
        float row_loss = (bcnt > 0) ? (bsum / (float)bcnt) : 0.0f;

        atomicAdd(&g_accum, (double)row_loss);
        __threadfence();
        unsigned int t = atomicAdd(&g_ticket, 1u);
        if (t == (unsigned int)(n_rows - 1)) {
            // Last row finalizer: read-and-reset state atomically so every
            // graph replay starts zeroed (matches zero-initialized first
            // call), then emit the mean.
            unsigned long long bits =
                atomicExch((unsigned long long*)&g_accum, 0ull);
            atomicExch(&g_ticket, 0u);
            double total = __longlong_as_double((long long)bits);
            out[0] = (float)(total / (double)n_rows);
        }
    }
}

extern "C" void kernel_launch(void* const* d_in, const int* in_sizes, int n_in,
                              void* d_out, int out_size) {
    const float* p = (const float*)d_in[0];
    const float* g = (const float*)d_in[1];
    float* out = (float*)d_out;

    const int total = in_sizes[0];
    const int n_rows = total / C_DIM;   // 16384

    mfl_fused_kernel<<<n_rows / 2, THREADS>>>(p, g, out, n_rows);
}

// round 15
// speedup vs baseline: 1.0592x; 1.0592x over previous
#include <cuda_runtime.h>

#define ESP 1e-12f
#define C_DIM 8192
#define THREADS 256

__device__ double        g_accum;   // zero-init; reset by finalizer each run
__device__ unsigned int  g_ticket;  // zero-init; reset by finalizer each run

__device__ __forceinline__ float fsqrt_approx(float x) {
    float r;
    asm("sqrt.approx.f32 %0, %1;" : "=f"(r) : "f"(x));
    return r;
}

// SESSION-FINAL KERNEL — best 149.6us @ 7.07 TB/s (88-89% of HBM spec),
// rel_err 6.7e-8, verified across 5 independent benches (149.6-151.5us).
//
// 14-round measured bracket — every axis probed in both directions:
//  - CTA shape: 256thr/1row WINS vs 128thr (R10, +3%), 512thr/2row (R14,
//    +5%), 256thr/2row (R4, +1.5%). (256 thr, 64KB traffic) matches the
//    HW distributor's balancing granularity.
//  - scheduling: dynamic grid WINS vs static persistent (R3, +11%: 16384
//    rows never divides 148 SMs) and ticket-persistent (R5, +3%: per-row
//    block-wide sync drains the load pipe).
//  - regs: __launch_bounds__(256,8) pins regs=32 -> 8 CTAs/SM; +3 regs
//    measured to cost ~6% DRAM utilization (R6).
//  - load width/policy: float4 .cs == LDG.256 == .nc at the
//    path-independent LTS/HBM ceiling (R8, R12).
//  - epilogue: plain smem reduce beats REDUX/dual-acc (reg pressure, R6).
//  - launch: fused single kernel, last-block finalize, atomically
//    self-resetting state (graph-replay deterministic).
// Residual ~11% DRAM idle = refresh + ramp/tail; not kernel-addressable.
__global__ void __launch_bounds__(THREADS, 8) mfl_fused_kernel(
    const float* __restrict__ p,
    const float* __restrict__ g,
    float* __restrict__ out,
    int n_rows)
{
    const int row = blockIdx.x;
    const float4* __restrict__ p4 =
        reinterpret_cast<const float4*>(p + (size_t)row * C_DIM);
    const float4* __restrict__ g4 =
        reinterpret_cast<const float4*>(g + (size_t)row * C_DIM);
    const int tid = threadIdx.x;

    float sum = 0.0f;
    int   cnt = 0;

    // C_DIM/4 = 2048 float4s, 256 threads -> 8 iterations. Streaming loads:
    // data is touched exactly once, keep it evict-first in L2.
    #pragma unroll
    for (int i = 0; i < 8; i++) {
        float4 pv = __ldcs(&p4[tid + i * THREADS]);
        float4 gv = __ldcs(&g4[tid + i * THREADS]);

        #pragma unroll
        for (int k = 0; k < 4; k++) {
            float pe = (&pv.x)[k];
            float ge = (&gv.x)[k];
            float a = fmaf(pe, ge, ESP);
            float b = fmaf(1.0f - pe, 1.0f - ge, ESP);
            float l = 1.0f - (fsqrt_approx(a) + fsqrt_approx(b));
            bool nz = (ge != 0.0f);
            sum += nz ? l : 0.0f;
            cnt += nz ? 1 : 0;
        }
    }

    // Warp reduction
    #pragma unroll
    for (int o = 16; o > 0; o >>= 1) {
        sum += __shfl_down_sync(0xffffffffu, sum, o);
        cnt += __shfl_down_sync(0xffffffffu, cnt, o);
    }

    __shared__ float s_sum[THREADS / 32];
    __shared__ int   s_cnt[THREADS / 32];
    const int wid = tid >> 5;
    const int lid = tid & 31;
    if (lid == 0) {
        s_sum[wid] = sum;
        s_cnt[wid] = cnt;
    }
    __syncthreads();

    if (tid == 0) {
        float bsum = 0.0f;
        int   bcnt = 0;
        #pragma unroll
        for (int w = 0; w < THREADS / 32; w++) {
            bsum += s_sum[w];
            bcnt += s_cnt[w];
        }
        float row_loss = (bcnt > 0) ? (bsum / (float)bcnt) : 0.0f;

        atomicAdd(&g_accum, (double)row_loss);
        __threadfence();
        unsigned int t = atomicAdd(&g_ticket, 1u);
        if (t == (unsigned int)(gridDim.x - 1)) {
            // Last block: read-and-reset accumulator + ticket atomically so
            // every graph replay starts from zeroed state (matches the
            // zero-initialized first call), then emit the result.
            unsigned long long bits =
                atomicExch((unsigned long long*)&g_accum, 0ull);
            atomicExch(&g_ticket, 0u);
            double total = __longlong_as_double((long long)bits);
            out[0] = (float)(total / (double)n_rows);
        }
    }
}

extern "C" void kernel_launch(void* const* d_in, const int* in_sizes, int n_in,
                              void* d_out, int out_size) {
    const float* p = (const float*)d_in[0];
    const float* g = (const float*)d_in[1];
    float* out = (float*)d_out;

    const int total = in_sizes[0];
    const int n_rows = total / C_DIM;   // 16384

    mfl_fused_kernel<<<n_rows, THREADS>>>(p, g, out, n_rows);
}